// round 9
// baseline (speedup 1.0000x reference)
#include <cuda_runtime.h>
#include <cstdint>
#include <math.h>

// ---------------- static device scratch (no allocation allowed) ----------------
#define MAXM 25088          // 256*98
__device__ float g_xa[MAXM * 512];
__device__ float g_xb[MAXM * 512];
__device__ float g_at[MAXM * 512];
__device__ float g_tp[MAXM * 512];
__device__ float g_qk[MAXM * 1536];
__device__ float g_hd[MAXM * 1024];
__device__ float g_wc[2 * 1536 * 512];     // conv weights pre-transposed [(l,tap,d_in), d_out]
__device__ float g_ct[512 * 8192];         // codebook transposed [d][k]
__device__ float g_cn[8192];               // ||c||^2
__device__ unsigned long long g_key[12544]; // fused VQ argmin keys

__device__ __forceinline__ float gelu_f(float x) {
    return 0.5f * x * (1.0f + erff(x * 0.7071067811865476f));
}

// ---------------- weight prep ----------------
__global__ void tr_convw(const float* __restrict__ w, float* __restrict__ wc) {
    int id = blockIdx.x * 256 + threadIdx.x;
    if (id >= 2 * 1536 * 512) return;
    int o  = id & 511;
    int kk = (id >> 9) % 1536;
    int l  = id / (1536 * 512);
    int tap = kk / 512, i = kk & 511;
    wc[id] = w[(((size_t)l * 512 + o) * 512 + i) * 3 + tap];
}

__global__ void tr_cb(const float* __restrict__ cb, float* __restrict__ cbT) {
    __shared__ float t[32][33];
    int n0 = blockIdx.x * 32, d0 = blockIdx.y * 32;
    for (int i = threadIdx.y; i < 32; i += 8)
        t[i][threadIdx.x] = cb[(size_t)(n0 + i) * 512 + d0 + threadIdx.x];
    __syncthreads();
    for (int i = threadIdx.y; i < 32; i += 8)
        cbT[(size_t)(d0 + i) * 8192 + n0 + threadIdx.x] = t[threadIdx.x][i];
}

// fused: blocks [0,1024) -> codebook norms (8 rows each); blocks [1024,1031) -> key init
__global__ void cnorm_key(const float* __restrict__ cb, float* __restrict__ cn,
                          unsigned long long* __restrict__ ky) {
    if (blockIdx.x >= 1024) {
        int i = (blockIdx.x - 1024) * 2048 + threadIdx.x * 8;
#pragma unroll
        for (int j = 0; j < 8; j++)
            if (i + j < 12544) ky[i + j] = ~0ull;
        return;
    }
    int warp = threadIdx.x >> 5, lane = threadIdx.x & 31;
    int row = blockIdx.x * 8 + warp;
    const float* rp = cb + (size_t)row * 512;
    float s = 0.f;
#pragma unroll
    for (int c = 0; c < 4; c++) {
        float4 v = *(const float4*)(rp + lane * 4 + c * 128);
        s += v.x * v.x + v.y * v.y + v.z * v.z + v.w * v.w;
    }
#pragma unroll
    for (int o = 16; o; o >>= 1) s += __shfl_xor_sync(0xffffffffu, s, o);
    if (!lane) cn[row] = s;
}

// ---------------- scalar fp32 GEMM: 128x128x8 tile, 8x8/thread ----------------
// Double-buffered smem, register-pipelined fragments, gmem prefetch distance 2.
// C[M,N] = A[M,Kd] @ Bw[Kd,N]  (+ epilogue)
// EPI: 0 = +bias | 1 = +bias,relu | 2 = +bias,gelu | 3 = +bias,+res | 4 = VQ fused argmin
// GATHER: A gathered from x[B,Tin,512] with 3-tap stride-2 causal conv indexing (Kd=1536)
template<int EPI, bool GATHER>
__global__ __launch_bounds__(256, 2) void gemm_k(
    const float* __restrict__ A, const float* __restrict__ Bw,
    const float* __restrict__ bias, const float* __restrict__ res,
    float* __restrict__ C, unsigned long long* __restrict__ keys,
    int M, int N, int Kd, int Tin, int Tout)
{
    __shared__ float As[2][8][132];   // [k][m], padded row -> conflict-free stores
    __shared__ float Bs[2][8][128];   // [k][n]
    int tid = threadIdx.x;
    int tx = tid & 15, ty = tid >> 4;
    int row0 = blockIdx.y * 128, col0 = blockIdx.x * 128;
    int ar = tid >> 1, kq = (tid & 1) * 4;   // A loader: row, 4-wide k-seg
    int bk = tid >> 5, bn = (tid & 31) * 4;  // B loader: k-row, 4-wide n-seg

    int gbase = 0, t2 = 0;
    if (GATHER) {
        int r = row0 + ar;
        int b2 = r / Tout;
        int t = r - b2 * Tout;
        gbase = b2 * Tin;
        t2 = 2 * t - 2;           // frame = gbase + clamp(t2 + tap)
    }
    const float* aPtr = A + (size_t)(row0 + ar) * Kd + kq;
    const float* bPtr = Bw + (size_t)bk * N + col0 + bn;

    auto loadA = [&](int k0, float4& dst) {
        if (GATHER) {
            int kk = k0 + kq;
            int tap = kk >> 9, d = kk & 511;
            int fr = t2 + tap;
            if (fr < 0) fr = 0;
            dst = *(const float4*)(A + (((size_t)(gbase + fr)) << 9) + d);
        } else {
            dst = *(const float4*)(aPtr + k0);
        }
    };
    auto loadB = [&](int k0, float4& dst) { dst = *(const float4*)(bPtr + (size_t)k0 * N); };
    auto stTiles = [&](int buf, const float4& va, const float4& vb) {
        As[buf][kq + 0][ar] = va.x;
        As[buf][kq + 1][ar] = va.y;
        As[buf][kq + 2][ar] = va.z;
        As[buf][kq + 3][ar] = va.w;
        *(float4*)&Bs[buf][bk][bn] = vb;
    };

    float acc[8][8];
#pragma unroll
    for (int i = 0; i < 8; i++)
#pragma unroll
        for (int j = 0; j < 8; j++) acc[i][j] = 0.f;

    int nT = Kd >> 3;
    float4 va[2], vb[2];
    loadA(0, va[0]); loadB(0, vb[0]);
    stTiles(0, va[0], vb[0]);
    if (nT > 1) { loadA(8, va[1]); loadB(8, vb[1]); }
    __syncthreads();

    float a[2][8], b[2][8];
    auto ldFrag = [&](int cur, int k, int slot) {
        *(float4*)(a[slot])     = *(const float4*)&As[cur][k][ty * 4];
        *(float4*)(a[slot] + 4) = *(const float4*)&As[cur][k][64 + ty * 4];
        *(float4*)(b[slot])     = *(const float4*)&Bs[cur][k][tx * 4];
        *(float4*)(b[slot] + 4) = *(const float4*)&Bs[cur][k][64 + tx * 4];
    };

    for (int t = 0; t < nT; t++) {
        int cur = t & 1;
        if (t + 2 < nT) { loadA((t + 2) * 8, va[cur]); loadB((t + 2) * 8, vb[cur]); }
        ldFrag(cur, 0, 0);
#pragma unroll
        for (int k = 0; k < 8; k++) {
            int s = k & 1;
            if (k < 7) ldFrag(cur, k + 1, s ^ 1);
#pragma unroll
            for (int i = 0; i < 8; i++)
#pragma unroll
                for (int j = 0; j < 8; j++) acc[i][j] += a[s][i] * b[s][j];
        }
        if (t + 1 < nT) {
            stTiles(cur ^ 1, va[(t + 1) & 1], vb[(t + 1) & 1]);
            __syncthreads();
        }
    }

    // ---------------- epilogue (quadrant layout: rows {ty*4, 64+ty*4}, cols {tx*4, 64+tx*4}) ----
    if (EPI == 4) {
        const float* cn = bias;
#pragma unroll
        for (int ih = 0; ih < 2; ih++) {
#pragma unroll
            for (int i = 0; i < 4; i++) {
                int r = row0 + ih * 64 + ty * 4 + i;
                unsigned long long best = ~0ull;
#pragma unroll
                for (int jh = 0; jh < 2; jh++) {
#pragma unroll
                    for (int j = 0; j < 4; j++) {
                        int n = col0 + jh * 64 + tx * 4 + j;
                        float s = cn[n] - 2.f * acc[ih * 4 + i][jh * 4 + j];
                        unsigned int u = __float_as_uint(s);
                        u = (u & 0x80000000u) ? ~u : (u | 0x80000000u);
                        unsigned long long key = ((unsigned long long)u << 32) | (unsigned int)n;
                        if (key < best) best = key;
                    }
                }
#pragma unroll
                for (int o = 8; o; o >>= 1) {
                    unsigned long long v = __shfl_xor_sync(0xffffffffu, best, o, 16);
                    if (v < best) best = v;
                }
                if (tx == 0) atomicMin(&keys[r], best);
            }
        }
        return;
    }

#pragma unroll
    for (int ih = 0; ih < 2; ih++) {
#pragma unroll
        for (int i = 0; i < 4; i++) {
            size_t r = (size_t)row0 + ih * 64 + ty * 4 + i;
#pragma unroll
            for (int jh = 0; jh < 2; jh++) {
                int c0 = col0 + jh * 64 + tx * 4;
                size_t cidx = r * (size_t)N + c0;
                float v[4];
#pragma unroll
                for (int j = 0; j < 4; j++) v[j] = acc[ih * 4 + i][jh * 4 + j] + bias[c0 + j];
                if (EPI == 1) {
#pragma unroll
                    for (int j = 0; j < 4; j++) v[j] = fmaxf(v[j], 0.f);
                }
                if (EPI == 2) {
#pragma unroll
                    for (int j = 0; j < 4; j++) v[j] = gelu_f(v[j]);
                }
                if (EPI == 3) {
                    float4 rv = *(const float4*)(res + cidx);
                    v[0] += rv.x; v[1] += rv.y; v[2] += rv.z; v[3] += rv.w;
                }
                *(float4*)(C + cidx) = make_float4(v[0], v[1], v[2], v[3]);
            }
        }
    }
}

// ---------------- causal attention (one block per (b,h)) ----------------
__global__ __launch_bounds__(256) void attn_kernel(const float* __restrict__ qkv,
                                                   float* __restrict__ out, int T) {
    extern __shared__ float smx[];
    float* Vs = smx;                 // T * 132
    float* Ks = Vs + T * 132;        // T * 129
    float* qs = Ks + T * 129;        // 8 * 128
    float* ps = qs + 8 * 128;        // 8 * 100
    int tid = threadIdx.x;
    int bh = blockIdx.x;
    int b = bh >> 2, h = bh & 3;
    const float* base = qkv + (size_t)b * T * 1536 + h * 128;

    for (int idx = tid; idx < T * 128; idx += 256) {
        int j = idx >> 7, d = idx & 127;
        const float* rowp = base + (size_t)j * 1536;
        Ks[j * 129 + d] = rowp[512 + d];
        Vs[j * 132 + d] = rowp[1024 + d];
    }
    __syncthreads();

    int warp = tid >> 5, lane = tid & 31;
    float* qw = qs + warp * 128;
    float* pw = ps + warp * 100;
    const float scale = 0.08838834764831845f;  // 1/sqrt(128)

    for (int i = warp; i < T; i += 8) {
        const float* qrow = base + (size_t)i * 1536;
#pragma unroll
        for (int c = 0; c < 4; c++) qw[lane + 32 * c] = qrow[lane + 32 * c];
        __syncwarp();
        float mx = -1e30f;
        for (int j = lane; j <= i; j += 32) {
            float s = 0.f;
            const float* kr = Ks + j * 129;
#pragma unroll 8
            for (int d = 0; d < 128; d++) s += qw[d] * kr[d];
            s *= scale;
            pw[j] = s;
            if (s > mx) mx = s;
        }
#pragma unroll
        for (int o = 16; o; o >>= 1) mx = fmaxf(mx, __shfl_xor_sync(0xffffffffu, mx, o));
        float sum = 0.f;
        for (int j = lane; j <= i; j += 32) {
            float e = expf(pw[j] - mx);
            pw[j] = e;
            sum += e;
        }
#pragma unroll
        for (int o = 16; o; o >>= 1) sum += __shfl_xor_sync(0xffffffffu, sum, o);
        float inv = 1.f / sum;
        __syncwarp();
        float4 acc = make_float4(0.f, 0.f, 0.f, 0.f);
        for (int j = 0; j <= i; j++) {
            float p = pw[j];
            float4 v = *(const float4*)(Vs + j * 132 + lane * 4);
            acc.x += p * v.x; acc.y += p * v.y; acc.z += p * v.z; acc.w += p * v.w;
        }
        acc.x *= inv; acc.y *= inv; acc.z *= inv; acc.w *= inv;
        *(float4*)(out + (size_t)(b * T + i) * 512 + h * 128 + lane * 4) = acc;
        __syncwarp();
    }
}

// ---------------- layernorm (one block of 128 threads per row) ----------------
__global__ __launch_bounds__(128) void ln_k(const float* __restrict__ in,
                                            const float* __restrict__ g,
                                            const float* __restrict__ bb,
                                            float* __restrict__ out) {
    __shared__ float red[4];
    int row = blockIdx.x, tid = threadIdx.x;
    const float4 x = *(const float4*)(in + (size_t)row * 512 + tid * 4);
    float s = x.x + x.y + x.z + x.w;
#pragma unroll
    for (int o = 16; o; o >>= 1) s += __shfl_xor_sync(0xffffffffu, s, o);
    if ((tid & 31) == 0) red[tid >> 5] = s;
    __syncthreads();
    float mean = (red[0] + red[1] + red[2] + red[3]) * 0.001953125f;
    float a0 = x.x - mean, a1 = x.y - mean, a2 = x.z - mean, a3 = x.w - mean;
    float q = a0 * a0 + a1 * a1 + a2 * a2 + a3 * a3;
#pragma unroll
    for (int o = 16; o; o >>= 1) q += __shfl_xor_sync(0xffffffffu, q, o);
    __syncthreads();
    if ((tid & 31) == 0) red[tid >> 5] = q;
    __syncthreads();
    float var = (red[0] + red[1] + red[2] + red[3]) * 0.001953125f;
    float rs = rsqrtf(var + 1e-5f);
    float4 gv = *(const float4*)(g + tid * 4);
    float4 bv = *(const float4*)(bb + tid * 4);
    float4 o4 = make_float4(a0 * rs * gv.x + bv.x, a1 * rs * gv.y + bv.y,
                            a2 * rs * gv.z + bv.z, a3 * rs * gv.w + bv.w);
    *(float4*)(out + (size_t)row * 512 + tid * 4) = o4;
}

// ---------------- VQ finalize: key -> idx, gather codebook ----------------
__global__ __launch_bounds__(128) void vq_fin(const unsigned long long* __restrict__ keys,
                                              const float* __restrict__ cb,
                                              float* __restrict__ oq,
                                              float* __restrict__ oi) {
    int row = blockIdx.x, tid = threadIdx.x;
    int idx = (int)(keys[row] & 0xffffffffu);
    float4 v = *(const float4*)(cb + (size_t)idx * 512 + tid * 4);
    *(float4*)(oq + (size_t)row * 512 + tid * 4) = v;
    if (tid == 0 && oi) oi[row] = (float)idx;
}

// ---------------- host launch ----------------
extern "C" void kernel_launch(void* const* d_in, const int* in_sizes, int n_in,
                              void* d_out, int out_size) {
    const float* motion = (const float*)d_in[0];
    const float* conv_w = (const float*)d_in[1];
    const float* conv_b = (const float*)d_in[2];
    const float* wqkv   = (const float*)d_in[3];
    const float* bqkv   = (const float*)d_in[4];
    const float* wo     = (const float*)d_in[5];
    const float* bo     = (const float*)d_in[6];
    const float* ln1g   = (const float*)d_in[7];
    const float* ln1b   = (const float*)d_in[8];
    const float* ln2g   = (const float*)d_in[9];
    const float* ln2b   = (const float*)d_in[10];
    const float* w1     = (const float*)d_in[11];
    const float* b1     = (const float*)d_in[12];
    const float* w2     = (const float*)d_in[13];
    const float* b2     = (const float*)d_in[14];
    const float* cbook  = (const float*)d_in[15];

    float *xa, *xb, *at, *tp, *qk, *hd, *wc, *ct, *cn;
    unsigned long long* ky;
    cudaGetSymbolAddress((void**)&xa, g_xa);
    cudaGetSymbolAddress((void**)&xb, g_xb);
    cudaGetSymbolAddress((void**)&at, g_at);
    cudaGetSymbolAddress((void**)&tp, g_tp);
    cudaGetSymbolAddress((void**)&qk, g_qk);
    cudaGetSymbolAddress((void**)&hd, g_hd);
    cudaGetSymbolAddress((void**)&wc, g_wc);
    cudaGetSymbolAddress((void**)&ct, g_ct);
    cudaGetSymbolAddress((void**)&cn, g_cn);
    cudaGetSymbolAddress((void**)&ky, g_key);

    cudaFuncSetAttribute(attn_kernel, cudaFuncAttributeMaxDynamicSharedMemorySize, 120 * 1024);

    // prep: order chosen so user-launch #3 is the conv GEMM (ncu -s 5 profiles it)
    tr_convw<<<(2 * 1536 * 512 + 255) / 256, 256>>>(conv_w, wc);          // 0
    tr_cb<<<dim3(8192 / 32, 512 / 32), dim3(32, 8)>>>(cbook, ct);          // 1
    cnorm_key<<<1031, 256>>>(cbook, cn, ky);                               // 2

    const float* px = motion;
    int Tin = 196;
    float* bufs[2] = {xa, xb};
    for (int l = 0; l < 2; l++) {
        int Tout = Tin >> 1;
        int M = 256 * Tout;
        float* cx = bufs[l];
        // causal half-downsample conv (implicit gather GEMM, Kd=1536) + bias + exact GELU
        gemm_k<2, true><<<dim3(512 / 128, M / 128), 256>>>(
            px, wc + (size_t)l * 1536 * 512, conv_b + l * 512, nullptr, cx, nullptr,
            M, 512, 1536, Tin, Tout);                                      // 3 (l=0)
        // QKV projection
        gemm_k<0, false><<<dim3(1536 / 128, M / 128), 256>>>(
            cx, wqkv + (size_t)l * 512 * 1536, bqkv + l * 1536, nullptr, qk, nullptr,
            M, 1536, 512, 0, 0);
        // causal attention
        size_t smem = (size_t)(Tout * 132 + Tout * 129 + 8 * 128 + 8 * 100) * 4;
        attn_kernel<<<256 * 4, 256, smem>>>(qk, at, Tout);
        // output proj + residual
        gemm_k<3, false><<<dim3(512 / 128, M / 128), 256>>>(
            at, wo + (size_t)l * 512 * 512, bo + l * 512, cx, tp, nullptr,
            M, 512, 512, 0, 0);
        ln_k<<<M, 128>>>(tp, ln1g + l * 512, ln1b + l * 512, cx);
        // FFN
        gemm_k<1, false><<<dim3(1024 / 128, M / 128), 256>>>(
            cx, w1 + (size_t)l * 512 * 1024, b1 + l * 1024, nullptr, hd, nullptr,
            M, 1024, 512, 0, 0);
        gemm_k<3, false><<<dim3(512 / 128, M / 128), 256>>>(
            hd, w2 + (size_t)l * 1024 * 512, b2 + l * 512, cx, tp, nullptr,
            M, 512, 1024, 0, 0);
        ln_k<<<M, 128>>>(tp, ln2g + l * 512, ln2b + l * 512, cx);
        px = cx;
        Tin = Tout;
    }

    // VQ: fused scores + per-row argmin via packed-key atomicMin (no score tensor)
    gemm_k<4, false><<<dim3(8192 / 128, 12544 / 128), 256>>>(
        px, ct, cn, nullptr, nullptr, ky, 12544, 8192, 512, 0, 0);

    float* out = (float*)d_out;
    float* oidx = (out_size >= 12544 * 512 + 12544) ? out + (size_t)12544 * 512 : nullptr;
    vq_fin<<<12544, 128>>>(ky, cbook, out, oidx);
}

// round 10
// speedup vs baseline: 1.0496x; 1.0496x over previous
#include <cuda_runtime.h>
#include <cstdint>
#include <math.h>

// ---------------- static device scratch (no allocation allowed) ----------------
#define MAXM 25088          // 256*98
__device__ float g_xa[MAXM * 512];
__device__ float g_xb[MAXM * 512];
__device__ float g_at[MAXM * 512];
__device__ float g_tp[MAXM * 512];
__device__ float g_qk[MAXM * 1536];
__device__ float g_hd[MAXM * 1024];
__device__ float g_wc[2 * 1536 * 512];     // conv weights pre-transposed [(l,tap,d_in), d_out]
__device__ float g_ct[512 * 8192];         // codebook transposed [d][k]
__device__ float g_cn[8192];               // ||c||^2
__device__ unsigned long long g_key[12544]; // fused VQ argmin keys

__device__ __forceinline__ float gelu_f(float x) {
    return 0.5f * x * (1.0f + erff(x * 0.7071067811865476f));
}

__device__ __forceinline__ uint32_t smem_u32(const void* p) {
    uint32_t a;
    asm("{ .reg .u64 t; cvta.to.shared.u64 t, %1; cvt.u32.u64 %0, t; }" : "=r"(a) : "l"(p));
    return a;
}
__device__ __forceinline__ void cp16(uint32_t dst, const void* src) {
    asm volatile("cp.async.cg.shared.global [%0], [%1], 16;" :: "r"(dst), "l"(src));
}
#define CP_COMMIT() asm volatile("cp.async.commit_group;" ::: "memory")
#define CP_WAIT2()  asm volatile("cp.async.wait_group 2;" ::: "memory")

// ---------------- weight prep ----------------
__global__ void tr_convw(const float* __restrict__ w, float* __restrict__ wc) {
    int id = blockIdx.x * 256 + threadIdx.x;
    if (id >= 2 * 1536 * 512) return;
    int o  = id & 511;
    int kk = (id >> 9) % 1536;
    int l  = id / (1536 * 512);
    int tap = kk / 512, i = kk & 511;
    wc[id] = w[(((size_t)l * 512 + o) * 512 + i) * 3 + tap];
}

__global__ void tr_cb(const float* __restrict__ cb, float* __restrict__ cbT) {
    __shared__ float t[32][33];
    int n0 = blockIdx.x * 32, d0 = blockIdx.y * 32;
    for (int i = threadIdx.y; i < 32; i += 8)
        t[i][threadIdx.x] = cb[(size_t)(n0 + i) * 512 + d0 + threadIdx.x];
    __syncthreads();
    for (int i = threadIdx.y; i < 32; i += 8)
        cbT[(size_t)(d0 + i) * 8192 + n0 + threadIdx.x] = t[threadIdx.x][i];
}

// fused: blocks [0,1024) -> codebook norms (8 rows each); blocks [1024,1031) -> key init
__global__ void cnorm_key(const float* __restrict__ cb, float* __restrict__ cn,
                          unsigned long long* __restrict__ ky) {
    if (blockIdx.x >= 1024) {
        int i = (blockIdx.x - 1024) * 2048 + threadIdx.x * 8;
#pragma unroll
        for (int j = 0; j < 8; j++)
            if (i + j < 12544) ky[i + j] = ~0ull;
        return;
    }
    int warp = threadIdx.x >> 5, lane = threadIdx.x & 31;
    int row = blockIdx.x * 8 + warp;
    const float* rp = cb + (size_t)row * 512;
    float s = 0.f;
#pragma unroll
    for (int c = 0; c < 4; c++) {
        float4 v = *(const float4*)(rp + lane * 4 + c * 128);
        s += v.x * v.x + v.y * v.y + v.z * v.z + v.w * v.w;
    }
#pragma unroll
    for (int o = 16; o; o >>= 1) s += __shfl_xor_sync(0xffffffffu, s, o);
    if (!lane) cn[row] = s;
}

// ---------------- scalar fp32 GEMM: 128x128x8 tile, 8x8/thread ----------------
// A: double-buffered smem via registers (dist 1). B: 4-stage cp.async ring (dist 3).
// Register-pipelined fragments. One __syncthreads per k-tile (top of loop).
// C[M,N] = A[M,Kd] @ Bw[Kd,N]  (+ epilogue)
// EPI: 0 = +bias | 1 = +bias,relu | 2 = +bias,gelu | 3 = +bias,+res | 4 = VQ fused argmin
// GATHER: A gathered from x[B,Tin,512] with 3-tap stride-2 causal conv indexing (Kd=1536)
template<int EPI, bool GATHER>
__global__ __launch_bounds__(256, 2) void gemm_k(
    const float* __restrict__ A, const float* __restrict__ Bw,
    const float* __restrict__ bias, const float* __restrict__ res,
    float* __restrict__ C, unsigned long long* __restrict__ keys,
    int M, int N, int Kd, int Tin, int Tout)
{
    __shared__ float As[2][8][132];   // [k][m], padded row -> conflict-free stores
    __shared__ float Bs[4][8][128];   // [stage][k][n], cp.async ring
    int tid = threadIdx.x;
    int tx = tid & 15, ty = tid >> 4;
    int row0 = blockIdx.y * 128, col0 = blockIdx.x * 128;
    int ar = tid >> 1, kq = (tid & 1) * 4;   // A loader: row, 4-wide k-seg
    int bk = tid >> 5, bn = (tid & 31) * 4;  // B loader: k-row, 4-wide n-seg (1 cp16/thread)

    int gbase = 0, t2 = 0;
    if (GATHER) {
        int r = row0 + ar;
        int b2 = r / Tout;
        int t = r - b2 * Tout;
        gbase = b2 * Tin;
        t2 = 2 * t - 2;           // frame = gbase + clamp(t2 + tap)
    }
    const float* aPtr = A + (size_t)(row0 + ar) * Kd + kq;
    const float* bPtr = Bw + (size_t)bk * N + col0 + bn;

    auto loadA = [&](int k0, float4& dst) {
        if (GATHER) {
            int kk = k0 + kq;
            int tap = kk >> 9, d = kk & 511;
            int fr = t2 + tap;
            if (fr < 0) fr = 0;
            dst = *(const float4*)(A + (((size_t)(gbase + fr)) << 9) + d);
        } else {
            dst = *(const float4*)(aPtr + k0);
        }
    };
    auto stA = [&](int buf, const float4& va) {
        As[buf][kq + 0][ar] = va.x;
        As[buf][kq + 1][ar] = va.y;
        As[buf][kq + 2][ar] = va.z;
        As[buf][kq + 3][ar] = va.w;
    };
    auto cpB = [&](int k0, int stg) {
        cp16(smem_u32(&Bs[stg][bk][bn]), bPtr + (size_t)k0 * N);
    };

    float acc[8][8];
#pragma unroll
    for (int i = 0; i < 8; i++)
#pragma unroll
        for (int j = 0; j < 8; j++) acc[i][j] = 0.f;

    int nT = Kd >> 3;
    // prologue: commit B tiles 0..2 (one group each), stage A tile 0 in smem, tile 1 in regs
    cpB(0, 0); CP_COMMIT();
    if (nT > 1) cpB(8, 1);
    CP_COMMIT();
    if (nT > 2) cpB(16, 2);
    CP_COMMIT();
    float4 va;
    loadA(0, va);
    stA(0, va);
    if (nT > 1) loadA(8, va);

    float a[2][8], b[2][8];
    auto ldFrag = [&](int abuf, int bstg, int k, int slot) {
        *(float4*)(a[slot])     = *(const float4*)&As[abuf][k][ty * 4];
        *(float4*)(a[slot] + 4) = *(const float4*)&As[abuf][k][64 + ty * 4];
        *(float4*)(b[slot])     = *(const float4*)&Bs[bstg][k][tx * 4];
        *(float4*)(b[slot] + 4) = *(const float4*)&Bs[bstg][k][64 + tx * 4];
    };

    for (int t = 0; t < nT; t++) {
        int cur = t & 1, bs = t & 3;
        CP_WAIT2();               // B[t] retired locally (2 newer groups may be in flight)
        __syncthreads();          // B[t] + A[t] visible to all; everyone done with t-1
        if (t + 3 < nT) cpB((t + 3) * 8, (t + 3) & 3);   // stage (t-1)&3: free after barrier
        CP_COMMIT();              // empty group near tail keeps wait_group accounting simple
        ldFrag(cur, bs, 0, 0);
#pragma unroll
        for (int k = 0; k < 8; k++) {
            int s = k & 1;
            if (k < 7) ldFrag(cur, bs, k + 1, s ^ 1);
#pragma unroll
            for (int i = 0; i < 8; i++)
#pragma unroll
                for (int j = 0; j < 8; j++) acc[i][j] += a[s][i] * b[s][j];
        }
        if (t + 1 < nT) {
            stA(cur ^ 1, va);
            if (t + 2 < nT) loadA((t + 2) * 8, va);
        }
    }

    // ---------------- epilogue (quadrant layout: rows {ty*4, 64+ty*4}, cols {tx*4, 64+tx*4}) ----
    if (EPI == 4) {
        const float* cn = bias;
#pragma unroll
        for (int ih = 0; ih < 2; ih++) {
#pragma unroll
            for (int i = 0; i < 4; i++) {
                int r = row0 + ih * 64 + ty * 4 + i;
                unsigned long long best = ~0ull;
#pragma unroll
                for (int jh = 0; jh < 2; jh++) {
#pragma unroll
                    for (int j = 0; j < 4; j++) {
                        int n = col0 + jh * 64 + tx * 4 + j;
                        float s = cn[n] - 2.f * acc[ih * 4 + i][jh * 4 + j];
                        unsigned int u = __float_as_uint(s);
                        u = (u & 0x80000000u) ? ~u : (u | 0x80000000u);
                        unsigned long long key = ((unsigned long long)u << 32) | (unsigned int)n;
                        if (key < best) best = key;
                    }
                }
#pragma unroll
                for (int o = 8; o; o >>= 1) {
                    unsigned long long v = __shfl_xor_sync(0xffffffffu, best, o, 16);
                    if (v < best) best = v;
                }
                if (tx == 0) atomicMin(&keys[r], best);
            }
        }
        return;
    }

#pragma unroll
    for (int ih = 0; ih < 2; ih++) {
#pragma unroll
        for (int i = 0; i < 4; i++) {
            size_t r = (size_t)row0 + ih * 64 + ty * 4 + i;
#pragma unroll
            for (int jh = 0; jh < 2; jh++) {
                int c0 = col0 + jh * 64 + tx * 4;
                size_t cidx = r * (size_t)N + c0;
                float v[4];
#pragma unroll
                for (int j = 0; j < 4; j++) v[j] = acc[ih * 4 + i][jh * 4 + j] + bias[c0 + j];
                if (EPI == 1) {
#pragma unroll
                    for (int j = 0; j < 4; j++) v[j] = fmaxf(v[j], 0.f);
                }
                if (EPI == 2) {
#pragma unroll
                    for (int j = 0; j < 4; j++) v[j] = gelu_f(v[j]);
                }
                if (EPI == 3) {
                    float4 rv = *(const float4*)(res + cidx);
                    v[0] += rv.x; v[1] += rv.y; v[2] += rv.z; v[3] += rv.w;
                }
                *(float4*)(C + cidx) = make_float4(v[0], v[1], v[2], v[3]);
            }
        }
    }
}

// ---------------- causal attention (one block per (b,h)) ----------------
__global__ __launch_bounds__(256) void attn_kernel(const float* __restrict__ qkv,
                                                   float* __restrict__ out, int T) {
    extern __shared__ float smx[];
    float* Vs = smx;                 // T * 132
    float* Ks = Vs + T * 132;        // T * 129
    float* qs = Ks + T * 129;        // 8 * 128
    float* ps = qs + 8 * 128;        // 8 * 100
    int tid = threadIdx.x;
    int bh = blockIdx.x;
    int b = bh >> 2, h = bh & 3;
    const float* base = qkv + (size_t)b * T * 1536 + h * 128;

    for (int idx = tid; idx < T * 128; idx += 256) {
        int j = idx >> 7, d = idx & 127;
        const float* rowp = base + (size_t)j * 1536;
        Ks[j * 129 + d] = rowp[512 + d];
        Vs[j * 132 + d] = rowp[1024 + d];
    }
    __syncthreads();

    int warp = tid >> 5, lane = tid & 31;
    float* qw = qs + warp * 128;
    float* pw = ps + warp * 100;
    const float scale = 0.08838834764831845f;  // 1/sqrt(128)

    for (int i = warp; i < T; i += 8) {
        const float* qrow = base + (size_t)i * 1536;
#pragma unroll
        for (int c = 0; c < 4; c++) qw[lane + 32 * c] = qrow[lane + 32 * c];
        __syncwarp();
        float mx = -1e30f;
        for (int j = lane; j <= i; j += 32) {
            float s = 0.f;
            const float* kr = Ks + j * 129;
#pragma unroll 8
            for (int d = 0; d < 128; d++) s += qw[d] * kr[d];
            s *= scale;
            pw[j] = s;
            if (s > mx) mx = s;
        }
#pragma unroll
        for (int o = 16; o; o >>= 1) mx = fmaxf(mx, __shfl_xor_sync(0xffffffffu, mx, o));
        float sum = 0.f;
        for (int j = lane; j <= i; j += 32) {
            float e = expf(pw[j] - mx);
            pw[j] = e;
            sum += e;
        }
#pragma unroll
        for (int o = 16; o; o >>= 1) sum += __shfl_xor_sync(0xffffffffu, sum, o);
        float inv = 1.f / sum;
        __syncwarp();
        float4 acc = make_float4(0.f, 0.f, 0.f, 0.f);
        for (int j = 0; j <= i; j++) {
            float p = pw[j];
            float4 v = *(const float4*)(Vs + j * 132 + lane * 4);
            acc.x += p * v.x; acc.y += p * v.y; acc.z += p * v.z; acc.w += p * v.w;
        }
        acc.x *= inv; acc.y *= inv; acc.z *= inv; acc.w *= inv;
        *(float4*)(out + (size_t)(b * T + i) * 512 + h * 128 + lane * 4) = acc;
        __syncwarp();
    }
}

// ---------------- layernorm (one block of 128 threads per row) ----------------
__global__ __launch_bounds__(128) void ln_k(const float* __restrict__ in,
                                            const float* __restrict__ g,
                                            const float* __restrict__ bb,
                                            float* __restrict__ out) {
    __shared__ float red[4];
    int row = blockIdx.x, tid = threadIdx.x;
    const float4 x = *(const float4*)(in + (size_t)row * 512 + tid * 4);
    float s = x.x + x.y + x.z + x.w;
#pragma unroll
    for (int o = 16; o; o >>= 1) s += __shfl_xor_sync(0xffffffffu, s, o);
    if ((tid & 31) == 0) red[tid >> 5] = s;
    __syncthreads();
    float mean = (red[0] + red[1] + red[2] + red[3]) * 0.001953125f;
    float a0 = x.x - mean, a1 = x.y - mean, a2 = x.z - mean, a3 = x.w - mean;
    float q = a0 * a0 + a1 * a1 + a2 * a2 + a3 * a3;
#pragma unroll
    for (int o = 16; o; o >>= 1) q += __shfl_xor_sync(0xffffffffu, q, o);
    __syncthreads();
    if ((tid & 31) == 0) red[tid >> 5] = q;
    __syncthreads();
    float var = (red[0] + red[1] + red[2] + red[3]) * 0.001953125f;
    float rs = rsqrtf(var + 1e-5f);
    float4 gv = *(const float4*)(g + tid * 4);
    float4 bv = *(const float4*)(bb + tid * 4);
    float4 o4 = make_float4(a0 * rs * gv.x + bv.x, a1 * rs * gv.y + bv.y,
                            a2 * rs * gv.z + bv.z, a3 * rs * gv.w + bv.w);
    *(float4*)(out + (size_t)row * 512 + tid * 4) = o4;
}

// ---------------- VQ finalize: key -> idx, gather codebook ----------------
__global__ __launch_bounds__(128) void vq_fin(const unsigned long long* __restrict__ keys,
                                              const float* __restrict__ cb,
                                              float* __restrict__ oq,
                                              float* __restrict__ oi) {
    int row = blockIdx.x, tid = threadIdx.x;
    int idx = (int)(keys[row] & 0xffffffffu);
    float4 v = *(const float4*)(cb + (size_t)idx * 512 + tid * 4);
    *(float4*)(oq + (size_t)row * 512 + tid * 4) = v;
    if (tid == 0 && oi) oi[row] = (float)idx;
}

// ---------------- host launch ----------------
extern "C" void kernel_launch(void* const* d_in, const int* in_sizes, int n_in,
                              void* d_out, int out_size) {
    const float* motion = (const float*)d_in[0];
    const float* conv_w = (const float*)d_in[1];
    const float* conv_b = (const float*)d_in[2];
    const float* wqkv   = (const float*)d_in[3];
    const float* bqkv   = (const float*)d_in[4];
    const float* wo     = (const float*)d_in[5];
    const float* bo     = (const float*)d_in[6];
    const float* ln1g   = (const float*)d_in[7];
    const float* ln1b   = (const float*)d_in[8];
    const float* ln2g   = (const float*)d_in[9];
    const float* ln2b   = (const float*)d_in[10];
    const float* w1     = (const float*)d_in[11];
    const float* b1     = (const float*)d_in[12];
    const float* w2     = (const float*)d_in[13];
    const float* b2     = (const float*)d_in[14];
    const float* cbook  = (const float*)d_in[15];

    float *xa, *xb, *at, *tp, *qk, *hd, *wc, *ct, *cn;
    unsigned long long* ky;
    cudaGetSymbolAddress((void**)&xa, g_xa);
    cudaGetSymbolAddress((void**)&xb, g_xb);
    cudaGetSymbolAddress((void**)&at, g_at);
    cudaGetSymbolAddress((void**)&tp, g_tp);
    cudaGetSymbolAddress((void**)&qk, g_qk);
    cudaGetSymbolAddress((void**)&hd, g_hd);
    cudaGetSymbolAddress((void**)&wc, g_wc);
    cudaGetSymbolAddress((void**)&ct, g_ct);
    cudaGetSymbolAddress((void**)&cn, g_cn);
    cudaGetSymbolAddress((void**)&ky, g_key);

    cudaFuncSetAttribute(attn_kernel, cudaFuncAttributeMaxDynamicSharedMemorySize, 120 * 1024);

    // prep: order chosen so user-launch #3 is the conv GEMM (ncu -s 5 profiles it)
    tr_convw<<<(2 * 1536 * 512 + 255) / 256, 256>>>(conv_w, wc);          // 0
    tr_cb<<<dim3(8192 / 32, 512 / 32), dim3(32, 8)>>>(cbook, ct);          // 1
    cnorm_key<<<1031, 256>>>(cbook, cn, ky);                               // 2

    const float* px = motion;
    int Tin = 196;
    float* bufs[2] = {xa, xb};
    for (int l = 0; l < 2; l++) {
        int Tout = Tin >> 1;
        int M = 256 * Tout;
        float* cx = bufs[l];
        // causal half-downsample conv (implicit gather GEMM, Kd=1536) + bias + exact GELU
        gemm_k<2, true><<<dim3(512 / 128, M / 128), 256>>>(
            px, wc + (size_t)l * 1536 * 512, conv_b + l * 512, nullptr, cx, nullptr,
            M, 512, 1536, Tin, Tout);                                      // 3 (l=0)
        // QKV projection
        gemm_k<0, false><<<dim3(1536 / 128, M / 128), 256>>>(
            cx, wqkv + (size_t)l * 512 * 1536, bqkv + l * 1536, nullptr, qk, nullptr,
            M, 1536, 512, 0, 0);
        // causal attention
        size_t smem = (size_t)(Tout * 132 + Tout * 129 + 8 * 128 + 8 * 100) * 4;
        attn_kernel<<<256 * 4, 256, smem>>>(qk, at, Tout);
        // output proj + residual
        gemm_k<3, false><<<dim3(512 / 128, M / 128), 256>>>(
            at, wo + (size_t)l * 512 * 512, bo + l * 512, cx, tp, nullptr,
            M, 512, 512, 0, 0);
        ln_k<<<M, 128>>>(tp, ln1g + l * 512, ln1b + l * 512, cx);
        // FFN
        gemm_k<1, false><<<dim3(1024 / 128, M / 128), 256>>>(
            cx, w1 + (size_t)l * 512 * 1024, b1 + l * 1024, nullptr, hd, nullptr,
            M, 1024, 512, 0, 0);
        gemm_k<3, false><<<dim3(512 / 128, M / 128), 256>>>(
            hd, w2 + (size_t)l * 1024 * 512, b2 + l * 512, cx, tp, nullptr,
            M, 512, 1024, 0, 0);
        ln_k<<<M, 128>>>(tp, ln2g + l * 512, ln2b + l * 512, cx);
        px = cx;
        Tin = Tout;
    }

    // VQ: fused scores + per-row argmin via packed-key atomicMin (no score tensor)
    gemm_k<4, false><<<dim3(8192 / 128, 12544 / 128), 256>>>(
        px, ct, cn, nullptr, nullptr, ky, 12544, 8192, 512, 0, 0);

    float* out = (float*)d_out;
    float* oidx = (out_size >= 12544 * 512 + 12544) ? out + (size_t)12544 * 512 : nullptr;
    vq_fin<<<12544, 128>>>(ky, cbook, out, oidx);
}

// round 11
// speedup vs baseline: 1.0669x; 1.0164x over previous
#include <cuda_runtime.h>
#include <cstdint>
#include <math.h>

// ---------------- static device scratch (no allocation allowed) ----------------
#define MAXM 25088          // 256*98
__device__ float g_xa[MAXM * 512];
__device__ float g_xb[MAXM * 512];
__device__ float g_at[MAXM * 512];
__device__ float g_tp[MAXM * 512];
__device__ float g_qk[MAXM * 1536];
__device__ float g_hd[MAXM * 1024];
__device__ float g_wc[2 * 1536 * 512];     // conv weights pre-transposed [(l,tap,d_in), d_out]
__device__ float g_ct[512 * 8192];         // codebook transposed [d][k]
__device__ float g_cn[8192];               // ||c||^2
__device__ unsigned long long g_key[12544]; // fused VQ argmin keys

__device__ __forceinline__ float gelu_f(float x) {
    return 0.5f * x * (1.0f + erff(x * 0.7071067811865476f));
}

#define FMA2(d, a, b) asm("fma.rn.f32x2 %0, %1, %2, %0;" : "+l"(d) : "l"(a), "l"(b))

// ---------------- weight prep ----------------
__global__ void tr_convw(const float* __restrict__ w, float* __restrict__ wc) {
    int id = blockIdx.x * 256 + threadIdx.x;
    if (id >= 2 * 1536 * 512) return;
    int o  = id & 511;
    int kk = (id >> 9) % 1536;
    int l  = id / (1536 * 512);
    int tap = kk / 512, i = kk & 511;
    wc[id] = w[(((size_t)l * 512 + o) * 512 + i) * 3 + tap];
}

__global__ void tr_cb(const float* __restrict__ cb, float* __restrict__ cbT) {
    __shared__ float t[32][33];
    int n0 = blockIdx.x * 32, d0 = blockIdx.y * 32;
    for (int i = threadIdx.y; i < 32; i += 8)
        t[i][threadIdx.x] = cb[(size_t)(n0 + i) * 512 + d0 + threadIdx.x];
    __syncthreads();
    for (int i = threadIdx.y; i < 32; i += 8)
        cbT[(size_t)(d0 + i) * 8192 + n0 + threadIdx.x] = t[threadIdx.x][i];
}

// fused: blocks [0,1024) -> codebook norms (8 rows each); blocks [1024,1031) -> key init
__global__ void cnorm_key(const float* __restrict__ cb, float* __restrict__ cn,
                          unsigned long long* __restrict__ ky) {
    if (blockIdx.x >= 1024) {
        int i = (blockIdx.x - 1024) * 2048 + threadIdx.x * 8;
#pragma unroll
        for (int j = 0; j < 8; j++)
            if (i + j < 12544) ky[i + j] = ~0ull;
        return;
    }
    int warp = threadIdx.x >> 5, lane = threadIdx.x & 31;
    int row = blockIdx.x * 8 + warp;
    const float* rp = cb + (size_t)row * 512;
    float s = 0.f;
#pragma unroll
    for (int c = 0; c < 4; c++) {
        float4 v = *(const float4*)(rp + lane * 4 + c * 128);
        s += v.x * v.x + v.y * v.y + v.z * v.z + v.w * v.w;
    }
#pragma unroll
    for (int o = 16; o; o >>= 1) s += __shfl_xor_sync(0xffffffffu, s, o);
    if (!lane) cn[row] = s;
}

// ---------------- scalar fp32 GEMM: 128x128x8 tile, 8x8/thread (R8 champion) ----------------
// Double-buffered smem, register-pipelined fragments.
// C[M,N] = A[M,Kd] @ Bw[Kd,N]  (+ epilogue)
// EPI: 0 = +bias | 1 = +bias,relu | 2 = +bias,gelu | 3 = +bias,+res
// GATHER: A gathered from x[B,Tin,512] with 3-tap stride-2 causal conv indexing (Kd=1536)
template<int EPI, bool GATHER>
__global__ __launch_bounds__(256, 2) void gemm_k(
    const float* __restrict__ A, const float* __restrict__ Bw,
    const float* __restrict__ bias, const float* __restrict__ res,
    float* __restrict__ C, int M, int N, int Kd, int Tin, int Tout)
{
    __shared__ float As[2][8][132];   // [k][m], padded row -> conflict-free stores
    __shared__ float Bs[2][8][128];   // [k][n]
    int tid = threadIdx.x;
    int tx = tid & 15, ty = tid >> 4;
    int row0 = blockIdx.y * 128, col0 = blockIdx.x * 128;
    int ar = tid >> 1, kq = (tid & 1) * 4;   // A loader: row, 4-wide k-seg
    int bk = tid >> 5, bn = (tid & 31) * 4;  // B loader: k-row, 4-wide n-seg

    int gbase = 0, t2 = 0;
    if (GATHER) {
        int r = row0 + ar;
        int b2 = r / Tout;
        int t = r - b2 * Tout;
        gbase = b2 * Tin;
        t2 = 2 * t - 2;           // frame = gbase + clamp(t2 + tap)
    }
    const float* aPtr = A + (size_t)(row0 + ar) * Kd + kq;
    const float* bPtr = Bw + (size_t)bk * N + col0 + bn;

    float4 va, vb;
    auto loadA = [&](int k0) {
        if (GATHER) {
            int kk = k0 + kq;
            int tap = kk >> 9, d = kk & 511;
            int fr = t2 + tap;
            if (fr < 0) fr = 0;
            va = *(const float4*)(A + (((size_t)(gbase + fr)) << 9) + d);
        } else {
            va = *(const float4*)(aPtr + k0);
        }
    };
    auto loadB = [&](int k0) { vb = *(const float4*)(bPtr + (size_t)k0 * N); };
    auto stTiles = [&](int buf) {
        As[buf][kq + 0][ar] = va.x;
        As[buf][kq + 1][ar] = va.y;
        As[buf][kq + 2][ar] = va.z;
        As[buf][kq + 3][ar] = va.w;
        *(float4*)&Bs[buf][bk][bn] = vb;
    };

    float acc[8][8];
#pragma unroll
    for (int i = 0; i < 8; i++)
#pragma unroll
        for (int j = 0; j < 8; j++) acc[i][j] = 0.f;

    loadA(0); loadB(0);
    stTiles(0);
    __syncthreads();

    float a[2][8], b[2][8];
    auto ldFrag = [&](int cur, int k, int slot) {
        *(float4*)(a[slot])     = *(const float4*)&As[cur][k][ty * 4];
        *(float4*)(a[slot] + 4) = *(const float4*)&As[cur][k][64 + ty * 4];
        *(float4*)(b[slot])     = *(const float4*)&Bs[cur][k][tx * 4];
        *(float4*)(b[slot] + 4) = *(const float4*)&Bs[cur][k][64 + tx * 4];
    };

    int nT = Kd >> 3;
    for (int t = 0; t < nT; t++) {
        int cur = t & 1;
        if (t + 1 < nT) { loadA((t + 1) * 8); loadB((t + 1) * 8); }
        ldFrag(cur, 0, 0);
#pragma unroll
        for (int k = 0; k < 8; k++) {
            int s = k & 1;
            if (k < 7) ldFrag(cur, k + 1, s ^ 1);
#pragma unroll
            for (int i = 0; i < 8; i++)
#pragma unroll
                for (int j = 0; j < 8; j++) acc[i][j] += a[s][i] * b[s][j];
        }
        if (t + 1 < nT) {
            stTiles(cur ^ 1);
            __syncthreads();
        }
    }

    // ---------------- epilogue (quadrant layout: rows {ty*4, 64+ty*4}, cols {tx*4, 64+tx*4}) ----
#pragma unroll
    for (int ih = 0; ih < 2; ih++) {
#pragma unroll
        for (int i = 0; i < 4; i++) {
            size_t r = (size_t)row0 + ih * 64 + ty * 4 + i;
#pragma unroll
            for (int jh = 0; jh < 2; jh++) {
                int c0 = col0 + jh * 64 + tx * 4;
                size_t cidx = r * (size_t)N + c0;
                float v[4];
#pragma unroll
                for (int j = 0; j < 4; j++) v[j] = acc[ih * 4 + i][jh * 4 + j] + bias[c0 + j];
                if (EPI == 1) {
#pragma unroll
                    for (int j = 0; j < 4; j++) v[j] = fmaxf(v[j], 0.f);
                }
                if (EPI == 2) {
#pragma unroll
                    for (int j = 0; j < 4; j++) v[j] = gelu_f(v[j]);
                }
                if (EPI == 3) {
                    float4 rv = *(const float4*)(res + cidx);
                    v[0] += rv.x; v[1] += rv.y; v[2] += rv.z; v[3] += rv.w;
                }
                *(float4*)(C + cidx) = make_float4(v[0], v[1], v[2], v[3]);
            }
        }
    }
}

// ---------------- VQ GEMM: f32x2 packed (FFMA2), 128x128x8, duplicated-A smem ----------------
// acc[i][jp] (u64) = {sum a_i*b_{2jp}, sum a_i*b_{2jp+1}} ; A stored duplicated so both
// operands come out of LDS.128 as ready u64 pairs — zero pack MOVs in the inner loop.
__global__ __launch_bounds__(256, 2) void gemm_vq(
    const float* __restrict__ A, const float* __restrict__ Bw,
    const float* __restrict__ cn, unsigned long long* __restrict__ keys,
    int M, int N, int Kd)
{
    __shared__ float As[2][8][268];   // duplicated A row: 256 floats + pad (268=67 f4)
    __shared__ float Bs[2][8][128];
    int tid = threadIdx.x;
    int tx = tid & 15, ty = tid >> 4;
    int row0 = blockIdx.y * 128, col0 = blockIdx.x * 128;
    int ar = tid >> 1, kq = (tid & 1) * 4;
    int bk = tid >> 5, bn = (tid & 31) * 4;
    const float* aPtr = A + (size_t)(row0 + ar) * Kd + kq;
    const float* bPtr = Bw + (size_t)bk * N + col0 + bn;

    float4 va, vb;
    auto loadA = [&](int k0) { va = *(const float4*)(aPtr + k0); };
    auto loadB = [&](int k0) { vb = *(const float4*)(bPtr + (size_t)k0 * N); };
    auto stTiles = [&](int buf) {
        *(float2*)&As[buf][kq + 0][2 * ar] = make_float2(va.x, va.x);
        *(float2*)&As[buf][kq + 1][2 * ar] = make_float2(va.y, va.y);
        *(float2*)&As[buf][kq + 2][2 * ar] = make_float2(va.z, va.z);
        *(float2*)&As[buf][kq + 3][2 * ar] = make_float2(va.w, va.w);
        *(float4*)&Bs[buf][bk][bn] = vb;
    };

    unsigned long long acc[8][4];
#pragma unroll
    for (int i = 0; i < 8; i++)
#pragma unroll
        for (int j = 0; j < 4; j++) acc[i][j] = 0ull;

    loadA(0); loadB(0);
    stTiles(0);
    __syncthreads();

    int nT = Kd >> 3;
    for (int t = 0; t < nT; t++) {
        int cur = t & 1;
        if (t + 1 < nT) { loadA((t + 1) * 8); loadB((t + 1) * 8); }
#pragma unroll
        for (int k = 0; k < 8; k++) {
            // A pairs {a_i,a_i}: 4 x LDS.128 (2 u64 each)
            ulonglong2 a01 = *(const ulonglong2*)&As[cur][k][ty * 8];
            ulonglong2 a23 = *(const ulonglong2*)&As[cur][k][ty * 8 + 4];
            ulonglong2 a45 = *(const ulonglong2*)&As[cur][k][128 + ty * 8];
            ulonglong2 a67 = *(const ulonglong2*)&As[cur][k][128 + ty * 8 + 4];
            unsigned long long ap[8] = {a01.x, a01.y, a23.x, a23.y,
                                        a45.x, a45.y, a67.x, a67.y};
            // B pairs {b_2j,b_2j+1}: 2 x LDS.128
            ulonglong2 b01 = *(const ulonglong2*)&Bs[cur][k][tx * 4];
            ulonglong2 b23 = *(const ulonglong2*)&Bs[cur][k][64 + tx * 4];
            unsigned long long bp[4] = {b01.x, b01.y, b23.x, b23.y};
#pragma unroll
            for (int i = 0; i < 8; i++)
#pragma unroll
                for (int j = 0; j < 4; j++) FMA2(acc[i][j], ap[i], bp[j]);
        }
        if (t + 1 < nT) {
            stTiles(cur ^ 1);
            __syncthreads();
        }
    }

    // epilogue: rows ih*64 + ty*4 + i ; cols: jp<2 -> tx*4 + jp*2, jp>=2 -> 64 + tx*4 + (jp-2)*2
#pragma unroll
    for (int ih = 0; ih < 2; ih++) {
#pragma unroll
        for (int i = 0; i < 4; i++) {
            int r = row0 + ih * 64 + ty * 4 + i;
            unsigned long long best = ~0ull;
#pragma unroll
            for (int jp = 0; jp < 4; jp++) {
                int n0 = col0 + ((jp < 2) ? (tx * 4 + jp * 2) : (64 + tx * 4 + (jp - 2) * 2));
                unsigned long long p = acc[ih * 4 + i][jp];
                float lo = __uint_as_float((unsigned int)(p & 0xffffffffu));
                float hi = __uint_as_float((unsigned int)(p >> 32));
                float s0 = cn[n0]     - 2.f * lo;
                float s1 = cn[n0 + 1] - 2.f * hi;
                unsigned int u0 = __float_as_uint(s0);
                u0 = (u0 & 0x80000000u) ? ~u0 : (u0 | 0x80000000u);
                unsigned int u1 = __float_as_uint(s1);
                u1 = (u1 & 0x80000000u) ? ~u1 : (u1 | 0x80000000u);
                unsigned long long k0 = ((unsigned long long)u0 << 32) | (unsigned int)n0;
                unsigned long long k1 = ((unsigned long long)u1 << 32) | (unsigned int)(n0 + 1);
                if (k0 < best) best = k0;
                if (k1 < best) best = k1;
            }
#pragma unroll
            for (int o = 8; o; o >>= 1) {
                unsigned long long v = __shfl_xor_sync(0xffffffffu, best, o, 16);
                if (v < best) best = v;
            }
            if (tx == 0) atomicMin(&keys[r], best);
        }
    }
}

// ---------------- causal attention (one block per (b,h)) ----------------
__global__ __launch_bounds__(256) void attn_kernel(const float* __restrict__ qkv,
                                                   float* __restrict__ out, int T) {
    extern __shared__ float smx[];
    float* Vs = smx;                 // T * 132
    float* Ks = Vs + T * 132;        // T * 129
    float* qs = Ks + T * 129;        // 8 * 128
    float* ps = qs + 8 * 128;        // 8 * 100
    int tid = threadIdx.x;
    int bh = blockIdx.x;
    int b = bh >> 2, h = bh & 3;
    const float* base = qkv + (size_t)b * T * 1536 + h * 128;

    for (int idx = tid; idx < T * 128; idx += 256) {
        int j = idx >> 7, d = idx & 127;
        const float* rowp = base + (size_t)j * 1536;
        Ks[j * 129 + d] = rowp[512 + d];
        Vs[j * 132 + d] = rowp[1024 + d];
    }
    __syncthreads();

    int warp = tid >> 5, lane = tid & 31;
    float* qw = qs + warp * 128;
    float* pw = ps + warp * 100;
    const float scale = 0.08838834764831845f;  // 1/sqrt(128)

    for (int i = warp; i < T; i += 8) {
        const float* qrow = base + (size_t)i * 1536;
#pragma unroll
        for (int c = 0; c < 4; c++) qw[lane + 32 * c] = qrow[lane + 32 * c];
        __syncwarp();
        float mx = -1e30f;
        for (int j = lane; j <= i; j += 32) {
            float s = 0.f;
            const float* kr = Ks + j * 129;
#pragma unroll 8
            for (int d = 0; d < 128; d++) s += qw[d] * kr[d];
            s *= scale;
            pw[j] = s;
            if (s > mx) mx = s;
        }
#pragma unroll
        for (int o = 16; o; o >>= 1) mx = fmaxf(mx, __shfl_xor_sync(0xffffffffu, mx, o));
        float sum = 0.f;
        for (int j = lane; j <= i; j += 32) {
            float e = expf(pw[j] - mx);
            pw[j] = e;
            sum += e;
        }
#pragma unroll
        for (int o = 16; o; o >>= 1) sum += __shfl_xor_sync(0xffffffffu, sum, o);
        float inv = 1.f / sum;
        __syncwarp();
        float4 acc = make_float4(0.f, 0.f, 0.f, 0.f);
        for (int j = 0; j <= i; j++) {
            float p = pw[j];
            float4 v = *(const float4*)(Vs + j * 132 + lane * 4);
            acc.x += p * v.x; acc.y += p * v.y; acc.z += p * v.z; acc.w += p * v.w;
        }
        acc.x *= inv; acc.y *= inv; acc.z *= inv; acc.w *= inv;
        *(float4*)(out + (size_t)(b * T + i) * 512 + h * 128 + lane * 4) = acc;
        __syncwarp();
    }
}

// ---------------- layernorm (one block of 128 threads per row) ----------------
__global__ __launch_bounds__(128) void ln_k(const float* __restrict__ in,
                                            const float* __restrict__ g,
                                            const float* __restrict__ bb,
                                            float* __restrict__ out) {
    __shared__ float red[4];
    int row = blockIdx.x, tid = threadIdx.x;
    const float4 x = *(const float4*)(in + (size_t)row * 512 + tid * 4);
    float s = x.x + x.y + x.z + x.w;
#pragma unroll
    for (int o = 16; o; o >>= 1) s += __shfl_xor_sync(0xffffffffu, s, o);
    if ((tid & 31) == 0) red[tid >> 5] = s;
    __syncthreads();
    float mean = (red[0] + red[1] + red[2] + red[3]) * 0.001953125f;
    float a0 = x.x - mean, a1 = x.y - mean, a2 = x.z - mean, a3 = x.w - mean;
    float q = a0 * a0 + a1 * a1 + a2 * a2 + a3 * a3;
#pragma unroll
    for (int o = 16; o; o >>= 1) q += __shfl_xor_sync(0xffffffffu, q, o);
    __syncthreads();
    if ((tid & 31) == 0) red[tid >> 5] = q;
    __syncthreads();
    float var = (red[0] + red[1] + red[2] + red[3]) * 0.001953125f;
    float rs = rsqrtf(var + 1e-5f);
    float4 gv = *(const float4*)(g + tid * 4);
    float4 bv = *(const float4*)(bb + tid * 4);
    float4 o4 = make_float4(a0 * rs * gv.x + bv.x, a1 * rs * gv.y + bv.y,
                            a2 * rs * gv.z + bv.z, a3 * rs * gv.w + bv.w);
    *(float4*)(out + (size_t)row * 512 + tid * 4) = o4;
}

// ---------------- VQ finalize: key -> idx, gather codebook ----------------
__global__ __launch_bounds__(128) void vq_fin(const unsigned long long* __restrict__ keys,
                                              const float* __restrict__ cb,
                                              float* __restrict__ oq,
                                              float* __restrict__ oi) {
    int row = blockIdx.x, tid = threadIdx.x;
    int idx = (int)(keys[row] & 0xffffffffu);
    float4 v = *(const float4*)(cb + (size_t)idx * 512 + tid * 4);
    *(float4*)(oq + (size_t)row * 512 + tid * 4) = v;
    if (tid == 0 && oi) oi[row] = (float)idx;
}

// ---------------- host launch ----------------
extern "C" void kernel_launch(void* const* d_in, const int* in_sizes, int n_in,
                              void* d_out, int out_size) {
    const float* motion = (const float*)d_in[0];
    const float* conv_w = (const float*)d_in[1];
    const float* conv_b = (const float*)d_in[2];
    const float* wqkv   = (const float*)d_in[3];
    const float* bqkv   = (const float*)d_in[4];
    const float* wo     = (const float*)d_in[5];
    const float* bo     = (const float*)d_in[6];
    const float* ln1g   = (const float*)d_in[7];
    const float* ln1b   = (const float*)d_in[8];
    const float* ln2g   = (const float*)d_in[9];
    const float* ln2b   = (const float*)d_in[10];
    const float* w1     = (const float*)d_in[11];
    const float* b1     = (const float*)d_in[12];
    const float* w2     = (const float*)d_in[13];
    const float* b2     = (const float*)d_in[14];
    const float* cbook  = (const float*)d_in[15];

    float *xa, *xb, *at, *tp, *qk, *hd, *wc, *ct, *cn;
    unsigned long long* ky;
    cudaGetSymbolAddress((void**)&xa, g_xa);
    cudaGetSymbolAddress((void**)&xb, g_xb);
    cudaGetSymbolAddress((void**)&at, g_at);
    cudaGetSymbolAddress((void**)&tp, g_tp);
    cudaGetSymbolAddress((void**)&qk, g_qk);
    cudaGetSymbolAddress((void**)&hd, g_hd);
    cudaGetSymbolAddress((void**)&wc, g_wc);
    cudaGetSymbolAddress((void**)&ct, g_ct);
    cudaGetSymbolAddress((void**)&cn, g_cn);
    cudaGetSymbolAddress((void**)&ky, g_key);

    cudaFuncSetAttribute(attn_kernel, cudaFuncAttributeMaxDynamicSharedMemorySize, 120 * 1024);

    // prep: order chosen so user-launch #3 is the conv GEMM (ncu -s 5 profiles it)
    tr_convw<<<(2 * 1536 * 512 + 255) / 256, 256>>>(conv_w, wc);          // 0
    tr_cb<<<dim3(8192 / 32, 512 / 32), dim3(32, 8)>>>(cbook, ct);          // 1
    cnorm_key<<<1031, 256>>>(cbook, cn, ky);                               // 2

    const float* px = motion;
    int Tin = 196;
    float* bufs[2] = {xa, xb};
    for (int l = 0; l < 2; l++) {
        int Tout = Tin >> 1;
        int M = 256 * Tout;
        float* cx = bufs[l];
        // causal half-downsample conv (implicit gather GEMM, Kd=1536) + bias + exact GELU
        gemm_k<2, true><<<dim3(512 / 128, M / 128), 256>>>(
            px, wc + (size_t)l * 1536 * 512, conv_b + l * 512, nullptr, cx,
            M, 512, 1536, Tin, Tout);                                      // 3 (l=0)
        // QKV projection
        gemm_k<0, false><<<dim3(1536 / 128, M / 128), 256>>>(
            cx, wqkv + (size_t)l * 512 * 1536, bqkv + l * 1536, nullptr, qk,
            M, 1536, 512, 0, 0);
        // causal attention
        size_t smem = (size_t)(Tout * 132 + Tout * 129 + 8 * 128 + 8 * 100) * 4;
        attn_kernel<<<256 * 4, 256, smem>>>(qk, at, Tout);
        // output proj + residual
        gemm_k<3, false><<<dim3(512 / 128, M / 128), 256>>>(
            at, wo + (size_t)l * 512 * 512, bo + l * 512, cx, tp,
            M, 512, 512, 0, 0);
        ln_k<<<M, 128>>>(tp, ln1g + l * 512, ln1b + l * 512, cx);
        // FFN
        gemm_k<1, false><<<dim3(1024 / 128, M / 128), 256>>>(
            cx, w1 + (size_t)l * 512 * 1024, b1 + l * 1024, nullptr, hd,
            M, 1024, 512, 0, 0);
        gemm_k<3, false><<<dim3(512 / 128, M / 128), 256>>>(
            hd, w2 + (size_t)l * 1024 * 512, b2 + l * 512, cx, tp,
            M, 512, 1024, 0, 0);
        ln_k<<<M, 128>>>(tp, ln2g + l * 512, ln2b + l * 512, cx);
        px = cx;
        Tin = Tout;
    }

    // VQ: f32x2-packed scores + fused per-row argmin (no score tensor)
    gemm_vq<<<dim3(8192 / 128, 12544 / 128), 256>>>(
        px, ct, cn, ky, 12544, 8192, 512);

    float* out = (float*)d_out;
    float* oidx = (out_size >= 12544 * 512 + 12544) ? out + (size_t)12544 * 512 : nullptr;
    vq_fin<<<12544, 128>>>(ky, cbook, out, oidx);
}

// round 12
// speedup vs baseline: 1.1448x; 1.0731x over previous
#include <cuda_runtime.h>
#include <cstdint>
#include <math.h>

// ---------------- static device scratch (no allocation allowed) ----------------
#define MAXM 25088          // 256*98
__device__ float g_xa[MAXM * 512];
__device__ float g_xb[MAXM * 512];
__device__ float g_at[MAXM * 512];
__device__ float g_tp[MAXM * 512];
__device__ float g_qk[MAXM * 1536];
__device__ float g_hd[MAXM * 1024];
__device__ float g_wc[2 * 1536 * 512];     // conv weights pre-transposed [(l,tap,d_in), d_out]
__device__ float g_ct[512 * 8192];         // codebook transposed [d][k]
__device__ float g_cn[8192];               // ||c||^2
__device__ unsigned long long g_key[12544]; // fused VQ argmin keys

__device__ __forceinline__ float gelu_f(float x) {
    return 0.5f * x * (1.0f + erff(x * 0.7071067811865476f));
}

// ---------------- weight prep ----------------
__global__ void tr_convw(const float* __restrict__ w, float* __restrict__ wc) {
    int id = blockIdx.x * 256 + threadIdx.x;
    if (id >= 2 * 1536 * 512) return;
    int o  = id & 511;
    int kk = (id >> 9) % 1536;
    int l  = id / (1536 * 512);
    int tap = kk / 512, i = kk & 511;
    wc[id] = w[(((size_t)l * 512 + o) * 512 + i) * 3 + tap];
}

__global__ void tr_cb(const float* __restrict__ cb, float* __restrict__ cbT) {
    __shared__ float t[32][33];
    int n0 = blockIdx.x * 32, d0 = blockIdx.y * 32;
    for (int i = threadIdx.y; i < 32; i += 8)
        t[i][threadIdx.x] = cb[(size_t)(n0 + i) * 512 + d0 + threadIdx.x];
    __syncthreads();
    for (int i = threadIdx.y; i < 32; i += 8)
        cbT[(size_t)(d0 + i) * 8192 + n0 + threadIdx.x] = t[threadIdx.x][i];
}

// fused: blocks [0,1024) -> codebook norms (8 rows each); blocks [1024,1031) -> key init
__global__ void cnorm_key(const float* __restrict__ cb, float* __restrict__ cn,
                          unsigned long long* __restrict__ ky) {
    if (blockIdx.x >= 1024) {
        int i = (blockIdx.x - 1024) * 2048 + threadIdx.x * 8;
#pragma unroll
        for (int j = 0; j < 8; j++)
            if (i + j < 12544) ky[i + j] = ~0ull;
        return;
    }
    int warp = threadIdx.x >> 5, lane = threadIdx.x & 31;
    int row = blockIdx.x * 8 + warp;
    const float* rp = cb + (size_t)row * 512;
    float s = 0.f;
#pragma unroll
    for (int c = 0; c < 4; c++) {
        float4 v = *(const float4*)(rp + lane * 4 + c * 128);
        s += v.x * v.x + v.y * v.y + v.z * v.z + v.w * v.w;
    }
#pragma unroll
    for (int o = 16; o; o >>= 1) s += __shfl_xor_sync(0xffffffffu, s, o);
    if (!lane) cn[row] = s;
}

// ---------------- scalar fp32 GEMM: 128x128x8 tile, 8x8/thread (R8 champion) ----------------
// Double-buffered smem, register-pipelined fragments.
// C[M,N] = A[M,Kd] @ Bw[Kd,N]  (+ epilogue)
// EPI: 0 = +bias | 1 = +bias,relu | 2 = +bias,gelu | 3 = +bias,+res | 4 = VQ fused argmin
// GATHER: A gathered from x[B,Tin,512] with 3-tap stride-2 causal conv indexing (Kd=1536)
template<int EPI, bool GATHER>
__global__ __launch_bounds__(256, 2) void gemm_k(
    const float* __restrict__ A, const float* __restrict__ Bw,
    const float* __restrict__ bias, const float* __restrict__ res,
    float* __restrict__ C, unsigned long long* __restrict__ keys,
    int M, int N, int Kd, int Tin, int Tout)
{
    __shared__ float As[2][8][132];   // [k][m], padded row -> conflict-free stores
    __shared__ float Bs[2][8][128];   // [k][n]
    int tid = threadIdx.x;
    int tx = tid & 15, ty = tid >> 4;
    int row0 = blockIdx.y * 128, col0 = blockIdx.x * 128;
    int ar = tid >> 1, kq = (tid & 1) * 4;   // A loader: row, 4-wide k-seg
    int bk = tid >> 5, bn = (tid & 31) * 4;  // B loader: k-row, 4-wide n-seg

    int gbase = 0, t2 = 0;
    if (GATHER) {
        int r = row0 + ar;
        int b2 = r / Tout;
        int t = r - b2 * Tout;
        gbase = b2 * Tin;
        t2 = 2 * t - 2;           // frame = gbase + clamp(t2 + tap)
    }
    const float* aPtr = A + (size_t)(row0 + ar) * Kd + kq;
    const float* bPtr = Bw + (size_t)bk * N + col0 + bn;

    float4 va, vb;
    auto loadA = [&](int k0) {
        if (GATHER) {
            int kk = k0 + kq;
            int tap = kk >> 9, d = kk & 511;
            int fr = t2 + tap;
            if (fr < 0) fr = 0;
            va = *(const float4*)(A + (((size_t)(gbase + fr)) << 9) + d);
        } else {
            va = *(const float4*)(aPtr + k0);
        }
    };
    auto loadB = [&](int k0) { vb = *(const float4*)(bPtr + (size_t)k0 * N); };
    auto stTiles = [&](int buf) {
        As[buf][kq + 0][ar] = va.x;
        As[buf][kq + 1][ar] = va.y;
        As[buf][kq + 2][ar] = va.z;
        As[buf][kq + 3][ar] = va.w;
        *(float4*)&Bs[buf][bk][bn] = vb;
    };

    float acc[8][8];
#pragma unroll
    for (int i = 0; i < 8; i++)
#pragma unroll
        for (int j = 0; j < 8; j++) acc[i][j] = 0.f;

    loadA(0); loadB(0);
    stTiles(0);
    __syncthreads();

    float a[2][8], b[2][8];
    auto ldFrag = [&](int cur, int k, int slot) {
        *(float4*)(a[slot])     = *(const float4*)&As[cur][k][ty * 4];
        *(float4*)(a[slot] + 4) = *(const float4*)&As[cur][k][64 + ty * 4];
        *(float4*)(b[slot])     = *(const float4*)&Bs[cur][k][tx * 4];
        *(float4*)(b[slot] + 4) = *(const float4*)&Bs[cur][k][64 + tx * 4];
    };

    int nT = Kd >> 3;
    for (int t = 0; t < nT; t++) {
        int cur = t & 1;
        if (t + 1 < nT) { loadA((t + 1) * 8); loadB((t + 1) * 8); }
        ldFrag(cur, 0, 0);
#pragma unroll
        for (int k = 0; k < 8; k++) {
            int s = k & 1;
            if (k < 7) ldFrag(cur, k + 1, s ^ 1);
#pragma unroll
            for (int i = 0; i < 8; i++)
#pragma unroll
                for (int j = 0; j < 8; j++) acc[i][j] += a[s][i] * b[s][j];
        }
        if (t + 1 < nT) {
            stTiles(cur ^ 1);
            __syncthreads();
        }
    }

    // ---------------- epilogue (quadrant layout: rows {ty*4, 64+ty*4}, cols {tx*4, 64+tx*4}) ----
    if (EPI == 4) {
        const float* cn = bias;
#pragma unroll
        for (int ih = 0; ih < 2; ih++) {
#pragma unroll
            for (int i = 0; i < 4; i++) {
                int r = row0 + ih * 64 + ty * 4 + i;
                unsigned long long best = ~0ull;
#pragma unroll
                for (int jh = 0; jh < 2; jh++) {
#pragma unroll
                    for (int j = 0; j < 4; j++) {
                        int n = col0 + jh * 64 + tx * 4 + j;
                        float s = cn[n] - 2.f * acc[ih * 4 + i][jh * 4 + j];
                        unsigned int u = __float_as_uint(s);
                        u = (u & 0x80000000u) ? ~u : (u | 0x80000000u);
                        unsigned long long key = ((unsigned long long)u << 32) | (unsigned int)n;
                        if (key < best) best = key;
                    }
                }
#pragma unroll
                for (int o = 8; o; o >>= 1) {
                    unsigned long long v = __shfl_xor_sync(0xffffffffu, best, o, 16);
                    if (v < best) best = v;
                }
                if (tx == 0) atomicMin(&keys[r], best);
            }
        }
        return;
    }

#pragma unroll
    for (int ih = 0; ih < 2; ih++) {
#pragma unroll
        for (int i = 0; i < 4; i++) {
            size_t r = (size_t)row0 + ih * 64 + ty * 4 + i;
#pragma unroll
            for (int jh = 0; jh < 2; jh++) {
                int c0 = col0 + jh * 64 + tx * 4;
                size_t cidx = r * (size_t)N + c0;
                float v[4];
#pragma unroll
                for (int j = 0; j < 4; j++) v[j] = acc[ih * 4 + i][jh * 4 + j] + bias[c0 + j];
                if (EPI == 1) {
#pragma unroll
                    for (int j = 0; j < 4; j++) v[j] = fmaxf(v[j], 0.f);
                }
                if (EPI == 2) {
#pragma unroll
                    for (int j = 0; j < 4; j++) v[j] = gelu_f(v[j]);
                }
                if (EPI == 3) {
                    float4 rv = *(const float4*)(res + cidx);
                    v[0] += rv.x; v[1] += rv.y; v[2] += rv.z; v[3] += rv.w;
                }
                *(float4*)(C + cidx) = make_float4(v[0], v[1], v[2], v[3]);
            }
        }
    }
}

// ---------------- causal attention (one block per (b,h)), float4 dot ----------------
__global__ __launch_bounds__(256) void attn_kernel(const float* __restrict__ qkv,
                                                   float* __restrict__ out, int T) {
    extern __shared__ float smx[];
    float* Vs = smx;                 // T * 132 (16B aligned, conflict-free f4 stride)
    float* Ks = Vs + T * 132;        // T * 132
    float* qs = Ks + T * 132;        // 8 * 128
    float* ps = qs + 8 * 128;        // 8 * 100
    int tid = threadIdx.x;
    int bh = blockIdx.x;
    int b = bh >> 2, h = bh & 3;
    const float* base = qkv + (size_t)b * T * 1536 + h * 128;

    for (int idx = tid; idx < T * 128; idx += 256) {
        int j = idx >> 7, d = idx & 127;
        const float* rowp = base + (size_t)j * 1536;
        Ks[j * 132 + d] = rowp[512 + d];
        Vs[j * 132 + d] = rowp[1024 + d];
    }
    __syncthreads();

    int warp = tid >> 5, lane = tid & 31;
    float* qw = qs + warp * 128;
    float* pw = ps + warp * 100;
    const float scale = 0.08838834764831845f;  // 1/sqrt(128)

    for (int i = warp; i < T; i += 8) {
        const float* qrow = base + (size_t)i * 1536;
#pragma unroll
        for (int c = 0; c < 4; c++) qw[lane + 32 * c] = qrow[lane + 32 * c];
        __syncwarp();
        const float4* qw4 = (const float4*)qw;
        float mx = -1e30f;
        for (int j = lane; j <= i; j += 32) {
            const float4* kr4 = (const float4*)(Ks + j * 132);
            float s0 = 0.f, s1 = 0.f, s2 = 0.f, s3 = 0.f;
#pragma unroll 8
            for (int d4 = 0; d4 < 32; d4++) {
                float4 q = qw4[d4];
                float4 k = kr4[d4];
                s0 += q.x * k.x;
                s1 += q.y * k.y;
                s2 += q.z * k.z;
                s3 += q.w * k.w;
            }
            float s = ((s0 + s1) + (s2 + s3)) * scale;
            pw[j] = s;
            if (s > mx) mx = s;
        }
#pragma unroll
        for (int o = 16; o; o >>= 1) mx = fmaxf(mx, __shfl_xor_sync(0xffffffffu, mx, o));
        float sum = 0.f;
        for (int j = lane; j <= i; j += 32) {
            float e = expf(pw[j] - mx);
            pw[j] = e;
            sum += e;
        }
#pragma unroll
        for (int o = 16; o; o >>= 1) sum += __shfl_xor_sync(0xffffffffu, sum, o);
        float inv = 1.f / sum;
        __syncwarp();
        float4 acc = make_float4(0.f, 0.f, 0.f, 0.f);
        for (int j = 0; j <= i; j++) {
            float p = pw[j];
            float4 v = *(const float4*)(Vs + j * 132 + lane * 4);
            acc.x += p * v.x; acc.y += p * v.y; acc.z += p * v.z; acc.w += p * v.w;
        }
        acc.x *= inv; acc.y *= inv; acc.z *= inv; acc.w *= inv;
        *(float4*)(out + (size_t)(b * T + i) * 512 + h * 128 + lane * 4) = acc;
        __syncwarp();
    }
}

// ---------------- layernorm: warp-per-row, 8 rows per 256-thread block ----------------
__global__ __launch_bounds__(256) void ln_k(const float* __restrict__ in,
                                            const float* __restrict__ g,
                                            const float* __restrict__ bb,
                                            float* __restrict__ out) {
    int warp = threadIdx.x >> 5, lane = threadIdx.x & 31;
    int row = blockIdx.x * 8 + warp;
    const float* rp = in + (size_t)row * 512;
    float4 x[4];
    float s = 0.f;
#pragma unroll
    for (int c = 0; c < 4; c++) {
        x[c] = *(const float4*)(rp + lane * 4 + c * 128);
        s += x[c].x + x[c].y + x[c].z + x[c].w;
    }
#pragma unroll
    for (int o = 16; o; o >>= 1) s += __shfl_xor_sync(0xffffffffu, s, o);
    float mean = s * 0.001953125f;
    float q = 0.f;
#pragma unroll
    for (int c = 0; c < 4; c++) {
        x[c].x -= mean; x[c].y -= mean; x[c].z -= mean; x[c].w -= mean;
        q += x[c].x * x[c].x + x[c].y * x[c].y + x[c].z * x[c].z + x[c].w * x[c].w;
    }
#pragma unroll
    for (int o = 16; o; o >>= 1) q += __shfl_xor_sync(0xffffffffu, q, o);
    float rs = rsqrtf(q * 0.001953125f + 1e-5f);
    float* op = out + (size_t)row * 512;
#pragma unroll
    for (int c = 0; c < 4; c++) {
        float4 gv = *(const float4*)(g + lane * 4 + c * 128);
        float4 bv = *(const float4*)(bb + lane * 4 + c * 128);
        float4 o4 = make_float4(x[c].x * rs * gv.x + bv.x, x[c].y * rs * gv.y + bv.y,
                                x[c].z * rs * gv.z + bv.z, x[c].w * rs * gv.w + bv.w);
        *(float4*)(op + lane * 4 + c * 128) = o4;
    }
}

// ---------------- VQ finalize: warp-per-row, 8 rows per block ----------------
__global__ __launch_bounds__(256) void vq_fin(const unsigned long long* __restrict__ keys,
                                              const float* __restrict__ cb,
                                              float* __restrict__ oq,
                                              float* __restrict__ oi) {
    int warp = threadIdx.x >> 5, lane = threadIdx.x & 31;
    int row = blockIdx.x * 8 + warp;
    int idx = (int)(keys[row] & 0xffffffffu);
    const float* crow = cb + (size_t)idx * 512;
    float* qrow = oq + (size_t)row * 512;
#pragma unroll
    for (int c = 0; c < 4; c++)
        *(float4*)(qrow + lane * 4 + c * 128) = *(const float4*)(crow + lane * 4 + c * 128);
    if (lane == 0 && oi) oi[row] = (float)idx;
}

// ---------------- host launch ----------------
extern "C" void kernel_launch(void* const* d_in, const int* in_sizes, int n_in,
                              void* d_out, int out_size) {
    const float* motion = (const float*)d_in[0];
    const float* conv_w = (const float*)d_in[1];
    const float* conv_b = (const float*)d_in[2];
    const float* wqkv   = (const float*)d_in[3];
    const float* bqkv   = (const float*)d_in[4];
    const float* wo     = (const float*)d_in[5];
    const float* bo     = (const float*)d_in[6];
    const float* ln1g   = (const float*)d_in[7];
    const float* ln1b   = (const float*)d_in[8];
    const float* ln2g   = (const float*)d_in[9];
    const float* ln2b   = (const float*)d_in[10];
    const float* w1     = (const float*)d_in[11];
    const float* b1     = (const float*)d_in[12];
    const float* w2     = (const float*)d_in[13];
    const float* b2     = (const float*)d_in[14];
    const float* cbook  = (const float*)d_in[15];

    float *xa, *xb, *at, *tp, *qk, *hd, *wc, *ct, *cn;
    unsigned long long* ky;
    cudaGetSymbolAddress((void**)&xa, g_xa);
    cudaGetSymbolAddress((void**)&xb, g_xb);
    cudaGetSymbolAddress((void**)&at, g_at);
    cudaGetSymbolAddress((void**)&tp, g_tp);
    cudaGetSymbolAddress((void**)&qk, g_qk);
    cudaGetSymbolAddress((void**)&hd, g_hd);
    cudaGetSymbolAddress((void**)&wc, g_wc);
    cudaGetSymbolAddress((void**)&ct, g_ct);
    cudaGetSymbolAddress((void**)&cn, g_cn);
    cudaGetSymbolAddress((void**)&ky, g_key);

    cudaFuncSetAttribute(attn_kernel, cudaFuncAttributeMaxDynamicSharedMemorySize, 120 * 1024);

    // prep: order chosen so user-launch #3 is the conv GEMM (ncu -s 5 profiles it)
    tr_convw<<<(2 * 1536 * 512 + 255) / 256, 256>>>(conv_w, wc);          // 0
    tr_cb<<<dim3(8192 / 32, 512 / 32), dim3(32, 8)>>>(cbook, ct);          // 1
    cnorm_key<<<1031, 256>>>(cbook, cn, ky);                               // 2

    const float* px = motion;
    int Tin = 196;
    float* bufs[2] = {xa, xb};
    for (int l = 0; l < 2; l++) {
        int Tout = Tin >> 1;
        int M = 256 * Tout;
        float* cx = bufs[l];
        // causal half-downsample conv (implicit gather GEMM, Kd=1536) + bias + exact GELU
        gemm_k<2, true><<<dim3(512 / 128, M / 128), 256>>>(
            px, wc + (size_t)l * 1536 * 512, conv_b + l * 512, nullptr, cx, nullptr,
            M, 512, 1536, Tin, Tout);                                      // 3 (l=0)
        // QKV projection
        gemm_k<0, false><<<dim3(1536 / 128, M / 128), 256>>>(
            cx, wqkv + (size_t)l * 512 * 1536, bqkv + l * 1536, nullptr, qk, nullptr,
            M, 1536, 512, 0, 0);
        // causal attention
        size_t smem = (size_t)(Tout * 132 * 2 + 8 * 128 + 8 * 100) * 4;
        attn_kernel<<<256 * 4, 256, smem>>>(qk, at, Tout);
        // output proj + residual
        gemm_k<3, false><<<dim3(512 / 128, M / 128), 256>>>(
            at, wo + (size_t)l * 512 * 512, bo + l * 512, cx, tp, nullptr,
            M, 512, 512, 0, 0);
        ln_k<<<M / 8, 256>>>(tp, ln1g + l * 512, ln1b + l * 512, cx);
        // FFN
        gemm_k<1, false><<<dim3(1024 / 128, M / 128), 256>>>(
            cx, w1 + (size_t)l * 512 * 1024, b1 + l * 1024, nullptr, hd, nullptr,
            M, 1024, 512, 0, 0);
        gemm_k<3, false><<<dim3(512 / 128, M / 128), 256>>>(
            hd, w2 + (size_t)l * 1024 * 512, b2 + l * 512, cx, tp, nullptr,
            M, 512, 1024, 0, 0);
        ln_k<<<M / 8, 256>>>(tp, ln2g + l * 512, ln2b + l * 512, cx);
        px = cx;
        Tin = Tout;
    }

    // VQ: fused scores + per-row argmin via packed-key atomicMin (no score tensor)
    gemm_k<4, false><<<dim3(8192 / 128, 12544 / 128), 256>>>(
        px, ct, cn, nullptr, nullptr, ky, 12544, 8192, 512, 0, 0);

    float* out = (float*)d_out;
    float* oidx = (out_size >= 12544 * 512 + 12544) ? out + (size_t)12544 * 512 : nullptr;
    vq_fin<<<12544 / 8, 256>>>(ky, cbook, out, oidx);
}